// round 5
// baseline (speedup 1.0000x reference)
#include <cuda_runtime.h>
#include <cstdint>

// ---------------------------------------------------------------------------
// x: (B=16, C=256, W=64, P=128) fp32; codebooks: (ns=4, K=256, sc=64) fp32
// idx[s,n] = argmin_k (|c_k|^2 - 2 x_n . c_k),  n = b*8192 + w*128 + p
// out[b, s*64+cc, w, p] = cb[s, idx[s, b*8192 + p*64 + w], cc]
// ---------------------------------------------------------------------------
#define NS 4
#define KCODES 256
#define SC 64
#define NVEC 131072
#define XB_STRIDE 2097152ull
#define CH_STRIDE 8192
#define TILE_M 256             // rows 0-127 tensor, 128-255 scalar-exact
#define NTILES_TOT 2048
#define NCTA 148
#define THR_COEF 4.2e-3f

__device__ int   g_idx[NS * NVEC];
__device__ float g_c2[NS * KCODES];
__device__ float g_cmax[NS];
__device__ int   g_rcnt4[NS];
__device__ int   g_rlist4[NS * NVEC];

// ---------------------------------------------------------------------------
__device__ __forceinline__ uint32_t tf32_of(float x) {
    uint32_t u;
    asm("cvt.rna.tf32.f32 %0, %1;" : "=r"(u) : "f"(x));
    return u;
}

#define MMA_TF32(d, a0, a1, a2, a3, b0, b1) \
    asm volatile("mma.sync.aligned.m16n8k8.row.col.f32.tf32.tf32.f32 " \
        "{%0,%1,%2,%3}, {%4,%5,%6,%7}, {%8,%9}, {%0,%1,%2,%3};" \
        : "+f"((d)[0]), "+f"((d)[1]), "+f"((d)[2]), "+f"((d)[3]) \
        : "r"(a0), "r"(a1), "r"(a2), "r"(a3), "r"(b0), "r"(b1))

// f32x2 helpers (scalar/rescue replicate round-1 arithmetic bit-exactly)
__device__ __forceinline__ unsigned long long pack2(float lo, float hi) {
    unsigned long long r;
    asm("mov.b64 %0, {%1, %2};" : "=l"(r) : "f"(lo), "f"(hi));
    return r;
}
__device__ __forceinline__ unsigned long long ffma2(unsigned long long a,
                                                    unsigned long long b,
                                                    unsigned long long c) {
    unsigned long long d;
    asm("fma.rn.f32x2 %0, %1, %2, %3;" : "=l"(d) : "l"(a), "l"(b), "l"(c));
    return d;
}
__device__ __forceinline__ void unpack2(unsigned long long v, float& lo, float& hi) {
    asm("mov.b64 {%0, %1}, %2;" : "=f"(lo), "=f"(hi) : "l"(v));
}

// ---------------------------------------------------------------------------
// kC2: per (s,k) |c_k|^2, per-s max row norm, reset rescue counters.
// ---------------------------------------------------------------------------
__global__ void kC2(const float* __restrict__ cb) {
    __shared__ float red[256];
    const int s = blockIdx.x;
    const int k = threadIdx.x;
    if (k < NS) g_rcnt4[k] = 0;
    const float4* r = (const float4*)(cb + ((size_t)s * KCODES + k) * SC);
    float acc = 0.0f;
#pragma unroll
    for (int j = 0; j < 16; j++) {
        float4 v = r[j];
        acc = fmaf(v.x, v.x, acc);
        acc = fmaf(v.y, v.y, acc);
        acc = fmaf(v.z, v.z, acc);
        acc = fmaf(v.w, v.w, acc);
    }
    g_c2[s * KCODES + k] = acc;
    red[k] = acc;
    __syncthreads();
    for (int st = 128; st > 0; st >>= 1) {
        if (k < st) red[k] = fmaxf(red[k], red[k + st]);
        __syncthreads();
    }
    if (k == 0) g_cmax[s] = sqrtf(red[0]);
}

// ---------------------------------------------------------------------------
// kArg: hybrid tensor+scalar persistent kernel.
// grid = 148, block = 512 (warps 0-7 tensor / 8-15 scalar-exact)
// smem: c2s[0,1024) | xn2[1024,1536) | partF[1536,2048) | partI[2048,2560)
//       Bhi(tf32)[4096,+73728) | cbS(exact)[77824,+65536) | Ahi[143360,+34816)
// ---------------------------------------------------------------------------
#define OFF_XN2  1024
#define OFF_PF   1536
#define OFF_PI   2048
#define OFF_B    4096
#define OFF_CBS  77824
#define OFF_A    143360
#define SMEM_MAIN 178176

__global__ __launch_bounds__(512, 1) void kArg(const float* __restrict__ x,
                                               const float* __restrict__ cb) {
    extern __shared__ __align__(16) char sm[];
    float* c2s   = (float*)sm;
    float* xn2   = (float*)(sm + OFF_XN2);
    float* partF = (float*)(sm + OFF_PF);
    int*   partI = (int*)(sm + OFF_PI);
    char*  Bhi   = sm + OFF_B;
    float* cbS   = (float*)(sm + OFF_CBS);
    char*  Ahi   = sm + OFF_A;

    const int tid  = threadIdx.x;
    const int w    = tid >> 5;
    const int lane = tid & 31;
    const int g    = lane >> 2;
    const int tg   = lane & 3;
    // scalar role decode
    const int sw    = w - 8;          // 0..7 for scalar warps
    const int pair  = sw >> 1;        // 0..3 row group
    const int khalf = sw & 1;         // 0: k 0-127, 1: k 128-255

    int   cur_s = -1;
    float cmax  = 0.0f;

    for (int t = blockIdx.x; t < NTILES_TOT; t += NCTA) {
        const int s    = t >> 9;
        const int tloc = t & 511;
        const int n0   = tloc * TILE_M;
        const int b    = n0 >> 13;
        const int m0   = n0 & 8191;

        if (s != cur_s) {
            __syncthreads();               // old B/cb fully consumed
            const float* bsrc = cb + (size_t)s * KCODES * SC;
#pragma unroll 4
            for (int e = tid; e < KCODES * SC; e += 512) {
                int n = e >> 6, k = e & 63;
                float v = __ldg(bsrc + e);
                cbS[e] = v;                // exact copy for scalar warps
                uint32_t pos = (uint32_t)((k & ~7) + ((k & 3) << 1) + ((k >> 2) & 1));
                *(uint32_t*)(Bhi + ((uint32_t)n * 72u + pos) * 4u) = tf32_of(v);
            }
            if (tid < KCODES) c2s[tid] = g_c2[s * KCODES + tid];
            cmax = __ldg(&g_cmax[s]);
            cur_s = s;
        }

        __syncthreads();                   // prev tile fully done (A, partials free)

        unsigned long long xr[SC / 2];     // scalar x row (live only on scalar path)
        if (w < 8) {
            // ---- stage A tensor tile (rows 0-127, tf32 + norms) ----
            const int m    = tid >> 1;     // 0..127
            const int half = tid & 1;
            const float* xp = x + (size_t)b * XB_STRIDE + (size_t)s * SC * CH_STRIDE
                            + m0 + m;
            const uint32_t mp = (uint32_t)((m & 0x70) + ((m & 7) << 1) + ((m >> 3) & 1));
            float nrm = 0.0f;
#pragma unroll 8
            for (int j = 0; j < 32; j++) {
                int c = half * 32 + j;
                float v = __ldg(xp + (size_t)c * CH_STRIDE);
                nrm = fmaf(v, v, nrm);
                *(uint32_t*)(Ahi + ((uint32_t)c * 136u + mp) * 4u) = tf32_of(v);
            }
            float o = __shfl_xor_sync(0xFFFFFFFFu, nrm, 1);
            if (!half) xn2[m] = nrm + o;
        } else {
            // ---- load exact x row for scalar lane (rows 128-255) ----
            const int m = m0 + 128 + pair * 32 + lane;
            const float* xp = x + (size_t)b * XB_STRIDE + (size_t)s * SC * CH_STRIDE + m;
#pragma unroll
            for (int j = 0; j < SC / 2; j++) {
                float lo = __ldg(xp + (size_t)(2 * j) * CH_STRIDE);
                float hi = __ldg(xp + (size_t)(2 * j + 1) * CH_STRIDE);
                xr[j] = pack2(lo, hi);
            }
        }
        __syncthreads();

        if (w < 8) {
            // ================= tensor path (rows 0-127) =================
            const char* abase = Ahi + (uint32_t)(w * 16 + 2 * g) * 4u;
            uint32_t af[8][4];
#pragma unroll
            for (int ks = 0; ks < 8; ks++) {
                uint2 p0 = *(const uint2*)(abase + (uint32_t)(ks * 8 + tg) * 544u);
                uint2 p1 = *(const uint2*)(abase + (uint32_t)(ks * 8 + tg + 4) * 544u);
                af[ks][0] = p0.x; af[ks][1] = p0.y; af[ks][2] = p1.x; af[ks][3] = p1.y;
            }

            float b1r0 = 3.4e38f, b2r0 = 3.4e38f, b1r1 = 3.4e38f, b2r1 = 3.4e38f;
            int bir0 = 0, bir1 = 0;

            for (int nc = 0; nc < 4; nc++) {
                float acc[8][4];
#pragma unroll
                for (int u = 0; u < 8; u++) {
                    acc[u][0] = 0.f; acc[u][1] = 0.f; acc[u][2] = 0.f; acc[u][3] = 0.f;
                }
                const char* bh = Bhi + ((uint32_t)(nc * 64 + g) * 72u
                                        + (uint32_t)tg * 2u) * 4u;
#pragma unroll
                for (int ks = 0; ks < 8; ks++) {
#pragma unroll
                    for (int sub = 0; sub < 8; sub++) {
                        uint2 bb = *(const uint2*)(bh + sub * 2304 + ks * 32);
                        MMA_TF32(acc[sub], af[ks][0], af[ks][1], af[ks][2], af[ks][3],
                                 bb.x, bb.y);
                    }
                }
#pragma unroll
                for (int sub = 0; sub < 8; sub++) {
                    int kb = nc * 64 + sub * 8 + 2 * tg;
                    float2 cc = *(const float2*)(c2s + kb);
                    float v00 = fmaf(-2.f, acc[sub][0], cc.x);
                    float v01 = fmaf(-2.f, acc[sub][1], cc.y);
                    float v10 = fmaf(-2.f, acc[sub][2], cc.x);
                    float v11 = fmaf(-2.f, acc[sub][3], cc.y);
                    if (v00 < b1r0) { b2r0 = b1r0; b1r0 = v00; bir0 = kb; }
                    else if (v00 < b2r0) { b2r0 = v00; }
                    if (v01 < b1r0) { b2r0 = b1r0; b1r0 = v01; bir0 = kb + 1; }
                    else if (v01 < b2r0) { b2r0 = v01; }
                    if (v10 < b1r1) { b2r1 = b1r1; b1r1 = v10; bir1 = kb; }
                    else if (v10 < b2r1) { b2r1 = v10; }
                    if (v11 < b1r1) { b2r1 = b1r1; b1r1 = v11; bir1 = kb + 1; }
                    else if (v11 < b2r1) { b2r1 = v11; }
                }
            }

#pragma unroll
            for (int d = 1; d <= 2; d <<= 1) {
                float o1 = __shfl_xor_sync(0xFFFFFFFFu, b1r0, d);
                float o2 = __shfl_xor_sync(0xFFFFFFFFu, b2r0, d);
                int   oi = __shfl_xor_sync(0xFFFFFFFFu, bir0, d);
                if (o1 < b1r0 || (o1 == b1r0 && oi < bir0)) {
                    b2r0 = fminf(b1r0, o2); b1r0 = o1; bir0 = oi;
                } else b2r0 = fminf(b2r0, o1);
                float p1 = __shfl_xor_sync(0xFFFFFFFFu, b1r1, d);
                float p2 = __shfl_xor_sync(0xFFFFFFFFu, b2r1, d);
                int   pi = __shfl_xor_sync(0xFFFFFFFFu, bir1, d);
                if (p1 < b1r1 || (p1 == b1r1 && pi < bir1)) {
                    b2r1 = fminf(b1r1, p2); b1r1 = p1; bir1 = pi;
                } else b2r1 = fminf(b2r1, p1);
            }

            if (tg == 0) {
                int r0 = w * 16 + g;
                int ng = n0 + r0;
                g_idx[s * NVEC + ng]     = bir0;
                g_idx[s * NVEC + ng + 8] = bir1;
                float thr0 = THR_COEF * sqrtf(xn2[r0])     * cmax;
                float thr1 = THR_COEF * sqrtf(xn2[r0 + 8]) * cmax;
                if (b2r0 - b1r0 < thr0) {
                    int sl = atomicAdd(&g_rcnt4[s], 1);
                    g_rlist4[s * NVEC + sl] = ng;
                }
                if (b2r1 - b1r1 < thr1) {
                    int sl = atomicAdd(&g_rcnt4[s], 1);
                    g_rlist4[s * NVEC + sl] = ng + 8;
                }
            }

            __syncthreads();               // match scalar warps' barrier
        } else {
            // ================= scalar exact path (rows 128-255) =================
            const int k0 = khalf * 128;
            float b1 = 3.4e38f;
            int   bi = 0;
#pragma unroll 2
            for (int k = 0; k < 128; k++) {
                const ulonglong2* row = (const ulonglong2*)(cbS + (size_t)(k0 + k) * SC);
                unsigned long long a0 = 0ull, a1 = 0ull;
#pragma unroll
                for (int j = 0; j < 16; j++) {
                    ulonglong2 v = row[j];
                    a0 = ffma2(xr[2 * j],     v.x, a0);
                    a1 = ffma2(xr[2 * j + 1], v.y, a1);
                }
                float l0, h0, l1, h1;
                unpack2(a0, l0, h0);
                unpack2(a1, l1, h1);
                float dot = (l0 + h0) + (l1 + h1);
                float sc = fmaf(-2.0f, dot, c2s[k0 + k]);
                if (sc < b1) { b1 = sc; bi = k0 + k; }
            }
            const int r2 = pair * 32 + lane;     // 0..127
            if (khalf == 1) {
                partF[r2] = b1;
                partI[r2] = bi;
            }
            __syncthreads();                     // partials visible (all warps hit this)
            if (khalf == 0) {
                float ob = partF[r2];
                int   oi = partI[r2];
                if (ob < b1) { b1 = ob; bi = oi; }   // strict <: lower half wins ties
                g_idx[s * NVEC + n0 + 128 + r2] = bi;
            }
        }
    }
}

// ---------------------------------------------------------------------------
// kRescue: exact fp32 full rescan of flagged (tensor-half) vectors.
// ---------------------------------------------------------------------------
#define SMEM_RESC 66560

__global__ __launch_bounds__(256) void kRescue(const float* __restrict__ x,
                                               const float* __restrict__ cb) {
    extern __shared__ __align__(16) char smr[];
    float* c2S = (float*)smr;
    float* cbS = (float*)(smr + 1024);

    const int sb  = blockIdx.x & 3;
    const int blk = blockIdx.x >> 2;
    const int tid = threadIdx.x;

    for (int e = tid; e < KCODES * SC; e += 256)
        cbS[e] = __ldg(cb + (size_t)sb * KCODES * SC + e);
    if (tid < KCODES) c2S[tid] = g_c2[sb * KCODES + tid];
    __syncthreads();

    const int cnt = g_rcnt4[sb];
    for (int i = blk * 256 + tid; i < cnt; i += 32 * 256) {
        const int n = g_rlist4[sb * NVEC + i];
        const int b = n >> 13, m = n & 8191;
        const float* xp = x + (size_t)b * XB_STRIDE + (size_t)sb * SC * CH_STRIDE + m;
        unsigned long long xr[SC / 2];
#pragma unroll
        for (int j = 0; j < SC / 2; j++) {
            float lo = __ldg(xp + (size_t)(2 * j) * CH_STRIDE);
            float hi = __ldg(xp + (size_t)(2 * j + 1) * CH_STRIDE);
            xr[j] = pack2(lo, hi);
        }
        float best = 3.4e38f;
        int bi = 0;
        for (int k = 0; k < KCODES; k++) {
            const ulonglong2* row = (const ulonglong2*)(cbS + (size_t)k * SC);
            unsigned long long a0 = 0ull, a1 = 0ull;
#pragma unroll
            for (int j = 0; j < 16; j++) {
                ulonglong2 v = row[j];
                a0 = ffma2(xr[2 * j],     v.x, a0);
                a1 = ffma2(xr[2 * j + 1], v.y, a1);
            }
            float l0, h0, l1, h1;
            unpack2(a0, l0, h0);
            unpack2(a1, l1, h1);
            float dot = (l0 + h0) + (l1 + h1);
            float sc = fmaf(-2.0f, dot, c2S[k]);
            if (sc < best) { best = sc; bi = k; }
        }
        g_idx[sb * NVEC + n] = bi;
    }
}

// ---------------------------------------------------------------------------
// kB: output gather (verified rel_err 0.0)
// ---------------------------------------------------------------------------
__global__ __launch_bounds__(256) void kB(const float* __restrict__ cb,
                                          float* __restrict__ out) {
    __shared__ float cbq[KCODES * 17];
    __shared__ int   idxt[64 * 66];

    const int bid  = blockIdx.x;
    const int pblk = bid & 1;
    const int cq   = (bid >> 1) & 3;
    const int b    = (bid >> 3) & 15;
    const int s    = bid >> 7;
    const int t    = threadIdx.x;

    {
        const float4* src = (const float4*)(cb + (size_t)s * KCODES * SC + (size_t)t * SC
                                               + cq * 16);
#pragma unroll
        for (int c4 = 0; c4 < 4; c4++) {
            float4 v = src[c4];
            cbq[t * 17 + c4 * 4 + 0] = v.x;
            cbq[t * 17 + c4 * 4 + 1] = v.y;
            cbq[t * 17 + c4 * 4 + 2] = v.z;
            cbq[t * 17 + c4 * 4 + 3] = v.w;
        }
    }
    {
        const int* src = g_idx + (size_t)s * NVEC + (size_t)b * 8192 + pblk * 4096;
#pragma unroll
        for (int r = 0; r < 16; r++) {
            int i  = r * 256 + t;
            int id = src[i];
            idxt[(i & 63) * 66 + (i >> 6)] = id;
        }
    }
    __syncthreads();

    const int lane = t & 31;
    const int warp = t >> 5;

    for (int w_o = warp; w_o < 64; w_o += 8) {
        int k0 = idxt[w_o * 66 + 2 * lane];
        int k1 = idxt[w_o * 66 + 2 * lane + 1];
        const float* r0 = cbq + k0 * 17;
        const float* r1 = cbq + k1 * 17;
        float* op = out + ((((size_t)b * 256 + s * 64 + cq * 16) * 64 + w_o) * 128)
                        + pblk * 64 + 2 * lane;
#pragma unroll
        for (int c = 0; c < 16; c++) {
            float2 v;
            v.x = r0[c];
            v.y = r1[c];
            *(float2*)(op + (size_t)c * CH_STRIDE) = v;
        }
    }
}

// ---------------------------------------------------------------------------
extern "C" void kernel_launch(void* const* d_in, const int* in_sizes, int n_in,
                              void* d_out, int out_size) {
    const float* x  = (const float*)d_in[0];
    const float* cb = (const float*)d_in[1];
    float* out = (float*)d_out;

    cudaFuncSetAttribute(kArg, cudaFuncAttributeMaxDynamicSharedMemorySize, SMEM_MAIN);
    cudaFuncSetAttribute(kRescue, cudaFuncAttributeMaxDynamicSharedMemorySize, SMEM_RESC);

    kC2<<<4, 256>>>(cb);
    kArg<<<NCTA, 512, SMEM_MAIN>>>(x, cb);
    kRescue<<<128, 256, SMEM_RESC>>>(x, cb);
    kB<<<512, 256>>>(cb, out);
}

// round 7
// speedup vs baseline: 1.3060x; 1.3060x over previous
#include <cuda_runtime.h>
#include <cstdint>

// ---------------------------------------------------------------------------
// x: (B=16, C=256, W=64, P=128) fp32; codebooks: (ns=4, K=256, sc=64) fp32
// idx[s,n] = argmin_k (|c_k|^2 - 2 x_n . c_k),  n = b*8192 + w*128 + p
// out[b, s*64+cc, w, p] = cb[s, idx[s, b*8192 + p*64 + w], cc]
// ---------------------------------------------------------------------------
#define NS 4
#define KCODES 256
#define SC 64
#define NVEC 131072
#define XB_STRIDE 2097152ull
#define CH_STRIDE 8192
#define TILE_M 128
#define NTILES_TOT 4096        // 4 s * 1024 tiles
#define NCTA 148
#define THR_COEF 4.2e-3f       // guaranteed TF32 argmin margin (see R4)

__device__ int   g_idx[NS * NVEC];
__device__ float g_c2[NS * KCODES];
__device__ int   g_cmax_bits[NS];   // max |c_k|^2 as monotonic int bits (c2 >= 0)
__device__ int   g_rcnt4[NS];
__device__ int   g_rlist4[NS * NVEC];

// ---------------------------------------------------------------------------
__device__ __forceinline__ uint32_t tf32_of(float x) {
    uint32_t u;
    asm("cvt.rna.tf32.f32 %0, %1;" : "=r"(u) : "f"(x));
    return u;
}

#define MMA_TF32(d, a0, a1, a2, a3, b0, b1) \
    asm volatile("mma.sync.aligned.m16n8k8.row.col.f32.tf32.tf32.f32 " \
        "{%0,%1,%2,%3}, {%4,%5,%6,%7}, {%8,%9}, {%0,%1,%2,%3};" \
        : "+f"((d)[0]), "+f"((d)[1]), "+f"((d)[2]), "+f"((d)[3]) \
        : "r"(a0), "r"(a1), "r"(a2), "r"(a3), "r"(b0), "r"(b1))

// f32x2 helpers (rescue replicates round-1 arithmetic bit-exactly)
__device__ __forceinline__ unsigned long long pack2(float lo, float hi) {
    unsigned long long r;
    asm("mov.b64 %0, {%1, %2};" : "=l"(r) : "f"(lo), "f"(hi));
    return r;
}
__device__ __forceinline__ unsigned long long ffma2(unsigned long long a,
                                                    unsigned long long b,
                                                    unsigned long long c) {
    unsigned long long d;
    asm("fma.rn.f32x2 %0, %1, %2, %3;" : "=l"(d) : "l"(a), "l"(b), "l"(c));
    return d;
}
__device__ __forceinline__ void unpack2(unsigned long long v, float& lo, float& hi) {
    asm("mov.b64 {%0, %1}, %2;" : "=f"(lo), "=f"(hi) : "l"(v));
}

// ---------------------------------------------------------------------------
// kInit: reset rescue counters and cmax accumulators.
// ---------------------------------------------------------------------------
__global__ void kInit() {
    int t = threadIdx.x;
    if (t < NS) {
        g_rcnt4[t] = 0;
        g_cmax_bits[t] = 0;       // 0 bits == +0.0f; all c2 > 0 will exceed it
    }
}

// ---------------------------------------------------------------------------
// kC2: |c_k|^2 per (s,k) — EXACT sequential fp32 chain, bit-identical to the
// round-1 kernel (this feeds the exact-rescue comparator; rounding order is
// part of the correctness contract — see R6 post-mortem).
// grid = 32, block = 32: one thread per codebook row.
// ---------------------------------------------------------------------------
__global__ void kC2(const float* __restrict__ cb) {
    int i = blockIdx.x * 32 + threadIdx.x;        // 0..1023 = s*256 + k
    const int s = i >> 8;
    const float4* r = (const float4*)(cb + (size_t)i * SC);
    float acc = 0.0f;
#pragma unroll
    for (int j = 0; j < 16; j++) {
        float4 v = r[j];
        acc = fmaf(v.x, v.x, acc);
        acc = fmaf(v.y, v.y, acc);
        acc = fmaf(v.z, v.z, acc);
        acc = fmaf(v.w, v.w, acc);
    }
    g_c2[i] = acc;
    atomicMax(&g_cmax_bits[s], __float_as_int(acc));   // c2 >= 0: bits monotonic
}

// ---------------------------------------------------------------------------
// kArg: persistent single-pass TF32 mma.sync, R3 loop shape.
// grid = 148, block = 256 (8 warps, 2/SMSP), dyn smem = 110592
// smem: c2s[0,1024) | xn2[1024,2048) (2x128) | Bhi[2048,+73728) | Ahi[75776,+34816)
// B row stride 72 floats, pairs (k,k+4) adjacent.
// A c-stride 136 floats, rows pair-interleaved (m, m+8) per 16-row warp chunk.
// ---------------------------------------------------------------------------
#define OFF_XN2 1024
#define OFF_B   2048
#define OFF_A   75776
#define SMEM_MAIN 110592

__global__ __launch_bounds__(256, 1) void kArg(const float* __restrict__ x,
                                               const float* __restrict__ cb) {
    extern __shared__ __align__(16) char sm[];
    float* c2s = (float*)sm;
    float* xn2 = (float*)(sm + OFF_XN2);
    char*  Bhi = sm + OFF_B;
    char*  Ahi = sm + OFF_A;

    const int tid  = threadIdx.x;
    const int w    = tid >> 5;
    const int lane = tid & 31;
    const int g    = lane >> 2;
    const int tg   = lane & 3;

    int   cur_s = -1;
    float cmax  = 0.0f;

    for (int t = blockIdx.x; t < NTILES_TOT; t += NCTA) {
        const int s    = t >> 10;
        const int tloc = t & 1023;
        const int n0   = tloc * TILE_M;
        const int b    = n0 >> 13;
        const int m0   = n0 & 8191;

        if (s != cur_s) {
            __syncthreads();               // old B fully consumed
            const float* bsrc = cb + (size_t)s * KCODES * SC;
#pragma unroll 4
            for (int e = tid; e < KCODES * SC; e += 256) {
                int n = e >> 6, k = e & 63;
                float v = __ldg(bsrc + e);
                uint32_t pos = (uint32_t)((k & ~7) + ((k & 3) << 1) + ((k >> 2) & 1));
                *(uint32_t*)(Bhi + ((uint32_t)n * 72u + pos) * 4u) = tf32_of(v);
            }
            c2s[tid] = g_c2[s * KCODES + tid];
            cmax = sqrtf(__int_as_float(__ldg(&g_cmax_bits[s])));
            cur_s = s;
        }

        __syncthreads();                   // prev tile's A fully consumed
        // ---- stage A (128 rows x 64 ch): thread -> fixed row m = tid&127 ----
        {
            const int m    = tid & 127;
            const int cof  = tid >> 7;     // 0: even channels, 1: odd channels
            const float* xp = x + (size_t)b * XB_STRIDE + (size_t)s * SC * CH_STRIDE
                            + m0 + m;
            const uint32_t mp = (uint32_t)((m & 0x70) + ((m & 7) << 1) + ((m >> 3) & 1));
            float nrm = 0.0f;
#pragma unroll
            for (int it = 0; it < 32; it++) {
                int c = cof + 2 * it;
                float v = __ldg(xp + (size_t)c * CH_STRIDE);
                nrm = fmaf(v, v, nrm);
                *(uint32_t*)(Ahi + ((uint32_t)c * 136u + mp) * 4u) = tf32_of(v);
            }
            xn2[cof * 128 + m] = nrm;      // halves summed at use site
        }
        __syncthreads();

        // ---- preload A fragments for the whole tile (K=64 -> 8 ksteps) ----
        const char* abase = Ahi + (uint32_t)(w * 16 + 2 * g) * 4u;
        uint32_t af[8][4];
#pragma unroll
        for (int ks = 0; ks < 8; ks++) {
            uint2 p0 = *(const uint2*)(abase + (uint32_t)(ks * 8 + tg) * 544u);
            uint2 p1 = *(const uint2*)(abase + (uint32_t)(ks * 8 + tg + 4) * 544u);
            af[ks][0] = p0.x; af[ks][1] = p0.y; af[ks][2] = p1.x; af[ks][3] = p1.y;
        }

        float b1r0 = 3.4e38f, b2r0 = 3.4e38f, b1r1 = 3.4e38f, b2r1 = 3.4e38f;
        int bir0 = 0, bir1 = 0;

        for (int nc = 0; nc < 4; nc++) {
            float acc[8][4];
#pragma unroll
            for (int u = 0; u < 8; u++) {
                acc[u][0] = 0.f; acc[u][1] = 0.f; acc[u][2] = 0.f; acc[u][3] = 0.f;
            }
            const char* bh = Bhi + ((uint32_t)(nc * 64 + g) * 72u + (uint32_t)tg * 2u) * 4u;
#pragma unroll
            for (int ks = 0; ks < 8; ks++) {
#pragma unroll
                for (int sub = 0; sub < 8; sub++) {
                    uint2 bb = *(const uint2*)(bh + sub * 2304 + ks * 32);
                    MMA_TF32(acc[sub], af[ks][0], af[ks][1], af[ks][2], af[ks][3],
                             bb.x, bb.y);
                }
            }
#pragma unroll
            for (int sub = 0; sub < 8; sub++) {
                int kb = nc * 64 + sub * 8 + 2 * tg;
                float2 cc = *(const float2*)(c2s + kb);
                float v00 = fmaf(-2.f, acc[sub][0], cc.x);
                float v01 = fmaf(-2.f, acc[sub][1], cc.y);
                float v10 = fmaf(-2.f, acc[sub][2], cc.x);
                float v11 = fmaf(-2.f, acc[sub][3], cc.y);
                if (v00 < b1r0) { b2r0 = b1r0; b1r0 = v00; bir0 = kb; }
                else if (v00 < b2r0) { b2r0 = v00; }
                if (v01 < b1r0) { b2r0 = b1r0; b1r0 = v01; bir0 = kb + 1; }
                else if (v01 < b2r0) { b2r0 = v01; }
                if (v10 < b1r1) { b2r1 = b1r1; b1r1 = v10; bir1 = kb; }
                else if (v10 < b2r1) { b2r1 = v10; }
                if (v11 < b1r1) { b2r1 = b1r1; b1r1 = v11; bir1 = kb + 1; }
                else if (v11 < b2r1) { b2r1 = v11; }
            }
        }

        // merge two-smallest across the 4-lane quad
#pragma unroll
        for (int d = 1; d <= 2; d <<= 1) {
            float o1 = __shfl_xor_sync(0xFFFFFFFFu, b1r0, d);
            float o2 = __shfl_xor_sync(0xFFFFFFFFu, b2r0, d);
            int   oi = __shfl_xor_sync(0xFFFFFFFFu, bir0, d);
            if (o1 < b1r0 || (o1 == b1r0 && oi < bir0)) {
                b2r0 = fminf(b1r0, o2); b1r0 = o1; bir0 = oi;
            } else b2r0 = fminf(b2r0, o1);
            float p1 = __shfl_xor_sync(0xFFFFFFFFu, b1r1, d);
            float p2 = __shfl_xor_sync(0xFFFFFFFFu, b2r1, d);
            int   pi = __shfl_xor_sync(0xFFFFFFFFu, bir1, d);
            if (p1 < b1r1 || (p1 == b1r1 && pi < bir1)) {
                b2r1 = fminf(b1r1, p2); b1r1 = p1; bir1 = pi;
            } else b2r1 = fminf(b2r1, p1);
        }

        if (tg == 0) {
            int r0 = w * 16 + g;
            int ng = n0 + r0;
            g_idx[s * NVEC + ng]     = bir0;
            g_idx[s * NVEC + ng + 8] = bir1;
            float thr0 = THR_COEF * sqrtf(xn2[r0]     + xn2[128 + r0])     * cmax;
            float thr1 = THR_COEF * sqrtf(xn2[r0 + 8] + xn2[128 + r0 + 8]) * cmax;
            if (b2r0 - b1r0 < thr0) {
                int sl = atomicAdd(&g_rcnt4[s], 1);
                g_rlist4[s * NVEC + sl] = ng;
            }
            if (b2r1 - b1r1 < thr1) {
                int sl = atomicAdd(&g_rcnt4[s], 1);
                g_rlist4[s * NVEC + sl] = ng + 8;
            }
        }
    }
}

// ---------------------------------------------------------------------------
// kRescue: exact fp32 full rescan of flagged vectors, codebook in smem.
// Arithmetic bit-identical to round 1 (including g_c2 rounding).
// ---------------------------------------------------------------------------
#define SMEM_RESC 66560

__global__ __launch_bounds__(256) void kRescue(const float* __restrict__ x,
                                               const float* __restrict__ cb) {
    extern __shared__ __align__(16) char smr[];
    float* c2S = (float*)smr;
    float* cbS = (float*)(smr + 1024);

    const int sb  = blockIdx.x & 3;
    const int blk = blockIdx.x >> 2;
    const int tid = threadIdx.x;

    for (int e = tid; e < KCODES * SC; e += 256)
        cbS[e] = __ldg(cb + (size_t)sb * KCODES * SC + e);
    if (tid < KCODES) c2S[tid] = g_c2[sb * KCODES + tid];
    __syncthreads();

    const int cnt = g_rcnt4[sb];
    for (int i = blk * 256 + tid; i < cnt; i += 32 * 256) {
        const int n = g_rlist4[sb * NVEC + i];
        const int b = n >> 13, m = n & 8191;
        const float* xp = x + (size_t)b * XB_STRIDE + (size_t)sb * SC * CH_STRIDE + m;
        unsigned long long xr[SC / 2];
#pragma unroll
        for (int j = 0; j < SC / 2; j++) {
            float lo = __ldg(xp + (size_t)(2 * j) * CH_STRIDE);
            float hi = __ldg(xp + (size_t)(2 * j + 1) * CH_STRIDE);
            xr[j] = pack2(lo, hi);
        }
        float best = 3.4e38f;
        int bi = 0;
        for (int k = 0; k < KCODES; k++) {
            const ulonglong2* row = (const ulonglong2*)(cbS + (size_t)k * SC);
            unsigned long long a0 = 0ull, a1 = 0ull;
#pragma unroll
            for (int j = 0; j < 16; j++) {
                ulonglong2 v = row[j];
                a0 = ffma2(xr[2 * j],     v.x, a0);
                a1 = ffma2(xr[2 * j + 1], v.y, a1);
            }
            float l0, h0, l1, h1;
            unpack2(a0, l0, h0);
            unpack2(a1, l1, h1);
            float dot = (l0 + h0) + (l1 + h1);
            float sc = fmaf(-2.0f, dot, c2S[k]);
            if (sc < best) { best = sc; bi = k; }
        }
        g_idx[sb * NVEC + n] = bi;
    }
}

// ---------------------------------------------------------------------------
// kB: output gather (verified rel_err 0.0)
// ---------------------------------------------------------------------------
__global__ __launch_bounds__(256) void kB(const float* __restrict__ cb,
                                          float* __restrict__ out) {
    __shared__ float cbq[KCODES * 17];
    __shared__ int   idxt[64 * 66];

    const int bid  = blockIdx.x;
    const int pblk = bid & 1;
    const int cq   = (bid >> 1) & 3;
    const int b    = (bid >> 3) & 15;
    const int s    = bid >> 7;
    const int t    = threadIdx.x;

    {
        const float4* src = (const float4*)(cb + (size_t)s * KCODES * SC + (size_t)t * SC
                                               + cq * 16);
#pragma unroll
        for (int c4 = 0; c4 < 4; c4++) {
            float4 v = src[c4];
            cbq[t * 17 + c4 * 4 + 0] = v.x;
            cbq[t * 17 + c4 * 4 + 1] = v.y;
            cbq[t * 17 + c4 * 4 + 2] = v.z;
            cbq[t * 17 + c4 * 4 + 3] = v.w;
        }
    }
    {
        const int* src = g_idx + (size_t)s * NVEC + (size_t)b * 8192 + pblk * 4096;
#pragma unroll
        for (int r = 0; r < 16; r++) {
            int i  = r * 256 + t;
            int id = src[i];
            idxt[(i & 63) * 66 + (i >> 6)] = id;
        }
    }
    __syncthreads();

    const int lane = t & 31;
    const int warp = t >> 5;

    for (int w_o = warp; w_o < 64; w_o += 8) {
        int k0 = idxt[w_o * 66 + 2 * lane];
        int k1 = idxt[w_o * 66 + 2 * lane + 1];
        const float* r0 = cbq + k0 * 17;
        const float* r1 = cbq + k1 * 17;
        float* op = out + ((((size_t)b * 256 + s * 64 + cq * 16) * 64 + w_o) * 128)
                        + pblk * 64 + 2 * lane;
#pragma unroll
        for (int c = 0; c < 16; c++) {
            float2 v;
            v.x = r0[c];
            v.y = r1[c];
            *(float2*)(op + (size_t)c * CH_STRIDE) = v;
        }
    }
}

// ---------------------------------------------------------------------------
extern "C" void kernel_launch(void* const* d_in, const int* in_sizes, int n_in,
                              void* d_out, int out_size) {
    const float* x  = (const float*)d_in[0];
    const float* cb = (const float*)d_in[1];
    float* out = (float*)d_out;

    cudaFuncSetAttribute(kArg, cudaFuncAttributeMaxDynamicSharedMemorySize, SMEM_MAIN);
    cudaFuncSetAttribute(kRescue, cudaFuncAttributeMaxDynamicSharedMemorySize, SMEM_RESC);

    kInit<<<1, 32>>>();
    kC2<<<32, 32>>>(cb);
    kArg<<<NCTA, 256, SMEM_MAIN>>>(x, cb);
    kRescue<<<128, 256, SMEM_RESC>>>(x, cb);
    kB<<<512, 256>>>(cb, out);
}

// round 8
// speedup vs baseline: 1.8021x; 1.3799x over previous
#include <cuda_runtime.h>
#include <cstdint>

// ---------------------------------------------------------------------------
// x: (B=16, C=256, W=64, P=128) fp32; codebooks: (ns=4, K=256, sc=64) fp32
// idx[s,n] = argmin_k (|c_k|^2 - 2 x_n . c_k),  n = b*8192 + w*128 + p
// out[b, s*64+cc, w, p] = cb[s, idx[s, b*8192 + p*64 + w], cc]
// ---------------------------------------------------------------------------
#define NS 4
#define KCODES 256
#define SC 64
#define NVEC 131072
#define XB_STRIDE 2097152ull
#define CH_STRIDE 8192
#define TILE_M 128
#define NTILES_TOT 4096
#define NCTA 148
#define THR_COEF 3.0e-3f   // needed: 2*(2^-10+eps)|x||c| ~ 1.97e-3; 50% margin

__device__ int   g_idx[NS * NVEC];
__device__ float g_c2[NS * KCODES];
__device__ int   g_cmax_bits[NS];
__device__ int   g_rcnt4[NS];
__device__ int   g_rlist4[NS * NVEC];

// ---------------------------------------------------------------------------
__device__ __forceinline__ uint32_t f16x2_of(float lo, float hi) {
    uint32_t u;  // cvt d, a, b -> hi = a, lo = b
    asm("cvt.rn.f16x2.f32 %0, %1, %2;" : "=r"(u) : "f"(hi), "f"(lo));
    return u;
}

#define MMA_F16(d, a0, a1, a2, a3, b0, b1) \
    asm volatile("mma.sync.aligned.m16n8k16.row.col.f32.f16.f16.f32 " \
        "{%0,%1,%2,%3}, {%4,%5,%6,%7}, {%8,%9}, {%0,%1,%2,%3};" \
        : "+f"((d)[0]), "+f"((d)[1]), "+f"((d)[2]), "+f"((d)[3]) \
        : "r"(a0), "r"(a1), "r"(a2), "r"(a3), "r"(b0), "r"(b1))

// f32x2 helpers (rescue replicates round-1 arithmetic bit-exactly)
__device__ __forceinline__ unsigned long long pack2(float lo, float hi) {
    unsigned long long r;
    asm("mov.b64 %0, {%1, %2};" : "=l"(r) : "f"(lo), "f"(hi));
    return r;
}
__device__ __forceinline__ unsigned long long ffma2(unsigned long long a,
                                                    unsigned long long b,
                                                    unsigned long long c) {
    unsigned long long d;
    asm("fma.rn.f32x2 %0, %1, %2, %3;" : "=l"(d) : "l"(a), "l"(b), "l"(c));
    return d;
}
__device__ __forceinline__ void unpack2(unsigned long long v, float& lo, float& hi) {
    asm("mov.b64 {%0, %1}, %2;" : "=f"(lo), "=f"(hi) : "l"(v));
}

// ---------------------------------------------------------------------------
__global__ void kInit() {
    int t = threadIdx.x;
    if (t < NS) {
        g_rcnt4[t] = 0;
        g_cmax_bits[t] = 0;
    }
}

// kC2 — EXACT sequential fp32 chain (feeds exact-rescue comparator; rounding
// order is part of the correctness contract, see R6 post-mortem).
__global__ void kC2(const float* __restrict__ cb) {
    int i = blockIdx.x * 32 + threadIdx.x;    // <<<32,32>>>: s*256 + k
    const int s = i >> 8;
    const float4* r = (const float4*)(cb + (size_t)i * SC);
    float acc = 0.0f;
#pragma unroll
    for (int j = 0; j < 16; j++) {
        float4 v = r[j];
        acc = fmaf(v.x, v.x, acc);
        acc = fmaf(v.y, v.y, acc);
        acc = fmaf(v.z, v.z, acc);
        acc = fmaf(v.w, v.w, acc);
    }
    g_c2[i] = acc;
    atomicMax(&g_cmax_bits[s], __float_as_int(acc));
}

// ---------------------------------------------------------------------------
// kArg: persistent FP16 m16n8k16 mma.sync + guaranteed-margin epilogue.
// grid = 148, block = 256 (8 warps, 2/SMSP), dyn smem = 56320
// smem: c2s[0,1024) | xn2[1024,2048) | Bh[2048,+36864) | Ah[38912,+17408)
// Bh: per code n, 36 u32 stride; entry = f16x2 (channels 2kp,2kp+1),
//     kp-pairs (kp,kp+4) adjacent: pos = (kp&~7)+((kp&3)<<1)+((kp>>2)&1).
// Ah: [kp][mp], 136 u32 stride; mp = (m&0x70)+((m&7)<<1)+((m>>3)&1).
// ---------------------------------------------------------------------------
#define OFF_XN2 1024
#define OFF_B   2048
#define OFF_A   38912
#define SMEM_MAIN 56320

__global__ __launch_bounds__(256, 1) void kArg(const float* __restrict__ x,
                                               const float* __restrict__ cb) {
    extern __shared__ __align__(16) char sm[];
    float* c2s = (float*)sm;
    float* xn2 = (float*)(sm + OFF_XN2);
    char*  Bh  = sm + OFF_B;
    char*  Ah  = sm + OFF_A;

    const int tid  = threadIdx.x;
    const int w    = tid >> 5;
    const int lane = tid & 31;
    const int g    = lane >> 2;
    const int tg   = lane & 3;

    int   cur_s = -1;
    float cmax  = 0.0f;

    for (int t = blockIdx.x; t < NTILES_TOT; t += NCTA) {
        const int s    = t >> 10;
        const int tloc = t & 1023;
        const int n0   = tloc * TILE_M;
        const int b    = n0 >> 13;
        const int m0   = n0 & 8191;

        if (s != cur_s) {
            __syncthreads();               // old B fully consumed
            const float* bsrc = cb + (size_t)s * KCODES * SC;
#pragma unroll 4
            for (int e = tid; e < KCODES * 32; e += 256) {  // 8192 f16x2 entries
                int n = e >> 5, kp = e & 31;
                float v0 = __ldg(bsrc + n * SC + 2 * kp);
                float v1 = __ldg(bsrc + n * SC + 2 * kp + 1);
                uint32_t pos = (uint32_t)((kp & ~7) + ((kp & 3) << 1) + ((kp >> 2) & 1));
                *(uint32_t*)(Bh + ((uint32_t)n * 36u + pos) * 4u) = f16x2_of(v0, v1);
            }
            c2s[tid] = g_c2[s * KCODES + tid];
            cmax = sqrtf(__int_as_float(__ldg(&g_cmax_bits[s])));
            cur_s = s;
        }

        __syncthreads();                   // prev tile's A fully consumed
        // ---- stage A (128 rows x 64 ch, fp16 pairs) ----
        {
            const int m  = tid & 127;
            const int kh = tid >> 7;       // kp half: 0 -> kp 0..15, 1 -> 16..31
            const float* xp = x + (size_t)b * XB_STRIDE + (size_t)s * SC * CH_STRIDE
                            + m0 + m;
            const uint32_t mp = (uint32_t)((m & 0x70) + ((m & 7) << 1) + ((m >> 3) & 1));
            float nrm = 0.0f;
#pragma unroll
            for (int j = 0; j < 16; j++) {
                int kp = kh * 16 + j;
                float v0 = __ldg(xp + (size_t)(2 * kp) * CH_STRIDE);
                float v1 = __ldg(xp + (size_t)(2 * kp + 1) * CH_STRIDE);
                nrm = fmaf(v0, v0, nrm);
                nrm = fmaf(v1, v1, nrm);
                *(uint32_t*)(Ah + ((uint32_t)kp * 136u + mp) * 4u) = f16x2_of(v0, v1);
            }
            xn2[kh * 128 + m] = nrm;
        }
        __syncthreads();

        // ---- preload A fragments (K=64 -> 4 ksteps of k16) ----
        const char* abase = Ah + (uint32_t)(w * 16 + 2 * g) * 4u;
        uint32_t af[4][4];
#pragma unroll
        for (int ks = 0; ks < 4; ks++) {
            uint2 p0 = *(const uint2*)(abase + (uint32_t)(ks * 8 + tg) * 544u);
            uint2 p1 = *(const uint2*)(abase + (uint32_t)(ks * 8 + tg + 4) * 544u);
            af[ks][0] = p0.x; af[ks][1] = p0.y; af[ks][2] = p1.x; af[ks][3] = p1.y;
        }

        float b1r0 = 3.4e38f, b2r0 = 3.4e38f, b1r1 = 3.4e38f, b2r1 = 3.4e38f;
        int bir0 = 0, bir1 = 0;

        for (int nc = 0; nc < 4; nc++) {
            float acc[8][4];
#pragma unroll
            for (int u = 0; u < 8; u++) {
                acc[u][0] = 0.f; acc[u][1] = 0.f; acc[u][2] = 0.f; acc[u][3] = 0.f;
            }
            const char* bh = Bh + ((uint32_t)(nc * 64 + g) * 36u + (uint32_t)tg * 2u) * 4u;
#pragma unroll
            for (int ks = 0; ks < 4; ks++) {
#pragma unroll
                for (int sub = 0; sub < 8; sub++) {
                    uint2 bb = *(const uint2*)(bh + sub * 1152 + ks * 32);
                    MMA_F16(acc[sub], af[ks][0], af[ks][1], af[ks][2], af[ks][3],
                            bb.x, bb.y);
                }
            }
#pragma unroll
            for (int sub = 0; sub < 8; sub++) {
                int kb = nc * 64 + sub * 8 + 2 * tg;
                float2 cc = *(const float2*)(c2s + kb);
                float v00 = fmaf(-2.f, acc[sub][0], cc.x);
                float v01 = fmaf(-2.f, acc[sub][1], cc.y);
                float v10 = fmaf(-2.f, acc[sub][2], cc.x);
                float v11 = fmaf(-2.f, acc[sub][3], cc.y);
                if (v00 < b1r0) { b2r0 = b1r0; b1r0 = v00; bir0 = kb; }
                else if (v00 < b2r0) { b2r0 = v00; }
                if (v01 < b1r0) { b2r0 = b1r0; b1r0 = v01; bir0 = kb + 1; }
                else if (v01 < b2r0) { b2r0 = v01; }
                if (v10 < b1r1) { b2r1 = b1r1; b1r1 = v10; bir1 = kb; }
                else if (v10 < b2r1) { b2r1 = v10; }
                if (v11 < b1r1) { b2r1 = b1r1; b1r1 = v11; bir1 = kb + 1; }
                else if (v11 < b2r1) { b2r1 = v11; }
            }
        }

        // merge two-smallest across the 4-lane quad
#pragma unroll
        for (int d = 1; d <= 2; d <<= 1) {
            float o1 = __shfl_xor_sync(0xFFFFFFFFu, b1r0, d);
            float o2 = __shfl_xor_sync(0xFFFFFFFFu, b2r0, d);
            int   oi = __shfl_xor_sync(0xFFFFFFFFu, bir0, d);
            if (o1 < b1r0 || (o1 == b1r0 && oi < bir0)) {
                b2r0 = fminf(b1r0, o2); b1r0 = o1; bir0 = oi;
            } else b2r0 = fminf(b2r0, o1);
            float p1 = __shfl_xor_sync(0xFFFFFFFFu, b1r1, d);
            float p2 = __shfl_xor_sync(0xFFFFFFFFu, b2r1, d);
            int   pi = __shfl_xor_sync(0xFFFFFFFFu, bir1, d);
            if (p1 < b1r1 || (p1 == b1r1 && pi < bir1)) {
                b2r1 = fminf(b1r1, p2); b1r1 = p1; bir1 = pi;
            } else b2r1 = fminf(b2r1, p1);
        }

        if (tg == 0) {
            int r0 = w * 16 + g;
            int ng = n0 + r0;
            g_idx[s * NVEC + ng]     = bir0;
            g_idx[s * NVEC + ng + 8] = bir1;
            float thr0 = THR_COEF * sqrtf(xn2[r0]     + xn2[128 + r0])     * cmax;
            float thr1 = THR_COEF * sqrtf(xn2[r0 + 8] + xn2[128 + r0 + 8]) * cmax;
            if (b2r0 - b1r0 < thr0) {
                int sl = atomicAdd(&g_rcnt4[s], 1);
                g_rlist4[s * NVEC + sl] = ng;
            }
            if (b2r1 - b1r1 < thr1) {
                int sl = atomicAdd(&g_rcnt4[s], 1);
                g_rlist4[s * NVEC + sl] = ng + 8;
            }
        }
    }
}

// ---------------------------------------------------------------------------
// kRescue: exact fp32 rescan (bit-identical per-code arithmetic to round 1),
// 2-code ILP, grid = 592 (148 blocks per s).
// smem: c2S 1KB + cbS 256 rows x 68-float stride (16B-aligned rows)
// ---------------------------------------------------------------------------
#define CB_STRIDE 68
#define SMEM_RESC (1024 + KCODES * CB_STRIDE * 4)

__global__ __launch_bounds__(256) void kRescue(const float* __restrict__ x,
                                               const float* __restrict__ cb) {
    extern __shared__ __align__(16) char smr[];
    float* c2S = (float*)smr;
    float* cbS = (float*)(smr + 1024);

    const int sb  = blockIdx.x & 3;
    const int blk = blockIdx.x >> 2;          // 0..147
    const int tid = threadIdx.x;

    for (int e = tid; e < KCODES * SC; e += 256) {
        int k = e >> 6, c = e & 63;
        cbS[k * CB_STRIDE + c] = __ldg(cb + (size_t)sb * KCODES * SC + e);
    }
    if (tid < KCODES) c2S[tid] = g_c2[sb * KCODES + tid];
    __syncthreads();

    const int cnt = g_rcnt4[sb];
    for (int i = blk * 256 + tid; i < cnt; i += NCTA * 256) {
        const int n = g_rlist4[sb * NVEC + i];
        const int b = n >> 13, m = n & 8191;
        const float* xp = x + (size_t)b * XB_STRIDE + (size_t)sb * SC * CH_STRIDE + m;
        unsigned long long xr[SC / 2];
#pragma unroll
        for (int j = 0; j < SC / 2; j++) {
            float lo = __ldg(xp + (size_t)(2 * j) * CH_STRIDE);
            float hi = __ldg(xp + (size_t)(2 * j + 1) * CH_STRIDE);
            xr[j] = pack2(lo, hi);
        }
        float best = 3.4e38f;
        int bi = 0;
        for (int k = 0; k < KCODES; k += 2) {   // 2 codes in flight (4 chains)
            const ulonglong2* rA = (const ulonglong2*)(cbS + (size_t)k * CB_STRIDE);
            const ulonglong2* rB = (const ulonglong2*)(cbS + (size_t)(k + 1) * CB_STRIDE);
            unsigned long long a0 = 0ull, a1 = 0ull, c0 = 0ull, c1 = 0ull;
#pragma unroll
            for (int j = 0; j < 16; j++) {
                ulonglong2 vA = rA[j];
                ulonglong2 vB = rB[j];
                a0 = ffma2(xr[2 * j],     vA.x, a0);
                a1 = ffma2(xr[2 * j + 1], vA.y, a1);
                c0 = ffma2(xr[2 * j],     vB.x, c0);
                c1 = ffma2(xr[2 * j + 1], vB.y, c1);
            }
            float l0, h0, l1, h1;
            unpack2(a0, l0, h0);
            unpack2(a1, l1, h1);
            float dotA = (l0 + h0) + (l1 + h1);
            float scA = fmaf(-2.0f, dotA, c2S[k]);
            unpack2(c0, l0, h0);
            unpack2(c1, l1, h1);
            float dotB = (l0 + h0) + (l1 + h1);
            float scB = fmaf(-2.0f, dotB, c2S[k + 1]);
            if (scA < best) { best = scA; bi = k; }       // k first: preserves
            if (scB < best) { best = scB; bi = k + 1; }   // first-min order
        }
        g_idx[sb * NVEC + n] = bi;
    }
}

// ---------------------------------------------------------------------------
// kB: output gather (verified rel_err 0.0)
// ---------------------------------------------------------------------------
__global__ __launch_bounds__(256) void kB(const float* __restrict__ cb,
                                          float* __restrict__ out) {
    __shared__ float cbq[KCODES * 17];
    __shared__ int   idxt[64 * 66];

    const int bid  = blockIdx.x;
    const int pblk = bid & 1;
    const int cq   = (bid >> 1) & 3;
    const int b    = (bid >> 3) & 15;
    const int s    = bid >> 7;
    const int t    = threadIdx.x;

    {
        const float4* src = (const float4*)(cb + (size_t)s * KCODES * SC + (size_t)t * SC
                                               + cq * 16);
#pragma unroll
        for (int c4 = 0; c4 < 4; c4++) {
            float4 v = src[c4];
            cbq[t * 17 + c4 * 4 + 0] = v.x;
            cbq[t * 17 + c4 * 4 + 1] = v.y;
            cbq[t * 17 + c4 * 4 + 2] = v.z;
            cbq[t * 17 + c4 * 4 + 3] = v.w;
        }
    }
    {
        const int* src = g_idx + (size_t)s * NVEC + (size_t)b * 8192 + pblk * 4096;
#pragma unroll
        for (int r = 0; r < 16; r++) {
            int i  = r * 256 + t;
            int id = src[i];
            idxt[(i & 63) * 66 + (i >> 6)] = id;
        }
    }
    __syncthreads();

    const int lane = t & 31;
    const int warp = t >> 5;

    for (int w_o = warp; w_o < 64; w_o += 8) {
        int k0 = idxt[w_o * 66 + 2 * lane];
        int k1 = idxt[w_o * 66 + 2 * lane + 1];
        const float* r0 = cbq + k0 * 17;
        const float* r1 = cbq + k1 * 17;
        float* op = out + ((((size_t)b * 256 + s * 64 + cq * 16) * 64 + w_o) * 128)
                        + pblk * 64 + 2 * lane;
#pragma unroll
        for (int c = 0; c < 16; c++) {
            float2 v;
            v.x = r0[c];
            v.y = r1[c];
            *(float2*)(op + (size_t)c * CH_STRIDE) = v;
        }
    }
}

// ---------------------------------------------------------------------------
extern "C" void kernel_launch(void* const* d_in, const int* in_sizes, int n_in,
                              void* d_out, int out_size) {
    const float* x  = (const float*)d_in[0];
    const float* cb = (const float*)d_in[1];
    float* out = (float*)d_out;

    cudaFuncSetAttribute(kArg, cudaFuncAttributeMaxDynamicSharedMemorySize, SMEM_MAIN);
    cudaFuncSetAttribute(kRescue, cudaFuncAttributeMaxDynamicSharedMemorySize, SMEM_RESC);

    kInit<<<1, 32>>>();
    kC2<<<32, 32>>>(cb);
    kArg<<<NCTA, 256, SMEM_MAIN>>>(x, cb);
    kRescue<<<NCTA * NS, 256, SMEM_RESC>>>(x, cb);
    kB<<<512, 256>>>(cb, out);
}